// round 16
// baseline (speedup 1.0000x reference)
#include <cuda_runtime.h>
#include <cuda_fp16.h>
#include <cstdint>
#include <cstddef>

// ---------------- scratch (all fp16) ----------------
__device__ __half h_q  [16777216];
__device__ __half h_k  [16777216];
__device__ __half h_v  [16777216];
__device__ __half h_Wq [16777216];
__device__ __half h_Wkv[ 8388608];     // [Wk ; Wv] concatenated rows
__device__ __half h_Wd [16777216];
__device__ __half h_Qp [16777216];
__device__ __half h_KVp[ 8388608];     // [tok][K(1024) | V(1024)]
__device__ __half h_ctx[16777216];
__device__ float2 g_trig[2048 * 64];

// ---------------- helpers ----------------
__device__ __forceinline__ uint32_t smem_u32(const void* p) {
    uint32_t a;
    asm("{ .reg .u64 t; cvta.to.shared.u64 t, %1; cvt.u32.u64 %0, t; }" : "=r"(a) : "l"(p));
    return a;
}
__device__ __forceinline__ void mma_f16(float* c, uint32_t a0, uint32_t a1,
                                        uint32_t a2, uint32_t a3,
                                        uint32_t b0, uint32_t b1) {
    asm volatile(
        "mma.sync.aligned.m16n8k16.row.col.f32.f16.f16.f32 "
        "{%0,%1,%2,%3}, {%4,%5,%6,%7}, {%8,%9}, {%0,%1,%2,%3};\n"
        : "+f"(c[0]), "+f"(c[1]), "+f"(c[2]), "+f"(c[3])
        : "r"(a0), "r"(a1), "r"(a2), "r"(a3), "r"(b0), "r"(b1));
}
__device__ __forceinline__ void ldsm_x4(uint32_t& r0, uint32_t& r1,
                                        uint32_t& r2, uint32_t& r3, uint32_t addr) {
    asm volatile("ldmatrix.sync.aligned.m8n8.x4.shared.b16 {%0,%1,%2,%3}, [%4];"
        : "=r"(r0), "=r"(r1), "=r"(r2), "=r"(r3) : "r"(addr));
}
__device__ __forceinline__ void ldsm_x4t(uint32_t& r0, uint32_t& r1,
                                         uint32_t& r2, uint32_t& r3, uint32_t addr) {
    asm volatile("ldmatrix.sync.aligned.m8n8.x4.trans.shared.b16 {%0,%1,%2,%3}, [%4];"
        : "=r"(r0), "=r"(r1), "=r"(r2), "=r"(r3) : "r"(addr));
}
__device__ __forceinline__ uint32_t ldcvt(const float* p) {
    float2 v = *(const float2*)p;
    __half2 h = __floats2half2_rn(v.x, v.y);
    return *(uint32_t*)&h;
}
#define CP_ASYNC16(dst, src) \
    asm volatile("cp.async.cg.shared.global [%0], [%1], 16;" :: "r"(dst), "l"(src) : "memory")
#define CP_COMMIT() asm volatile("cp.async.commit_group;" ::: "memory")
#define CP_WAIT1()  asm volatile("cp.async.wait_group 1;" ::: "memory")

// =========================================================================
// merged fp32 -> fp16 conversion (one launch)
// layout: q | k | v | Wq | Wk->Wkv[0:] | Wv->Wkv[4M:] | Wd
// =========================================================================
#define SEG_BIG   4194304
#define SEG_SMALL 1048576
#define F2H_TOTAL (5 * SEG_BIG + 2 * SEG_SMALL)

__global__ void f2h_all(const float4* __restrict__ q,  const float4* __restrict__ k,
                        const float4* __restrict__ v,  const float4* __restrict__ Wq,
                        const float4* __restrict__ Wk, const float4* __restrict__ Wv,
                        const float4* __restrict__ Wd)
{
    long i = (long)blockIdx.x * blockDim.x + threadIdx.x;
    if (i >= F2H_TOTAL) return;
    const float4* src;
    uint2* dst;
    long o = i;
    if (o < SEG_BIG)                    { src = q;  dst = (uint2*)h_q; }
    else if ((o -= SEG_BIG) < SEG_BIG)  { src = k;  dst = (uint2*)h_k; }
    else if ((o -= SEG_BIG) < SEG_BIG)  { src = v;  dst = (uint2*)h_v; }
    else if ((o -= SEG_BIG) < SEG_BIG)  { src = Wq; dst = (uint2*)h_Wq; }
    else if ((o -= SEG_BIG) < SEG_SMALL){ src = Wk; dst = (uint2*)h_Wkv; }
    else if ((o -= SEG_SMALL) < SEG_SMALL){ src = Wv; dst = (uint2*)h_Wkv + SEG_SMALL; }
    else { o -= SEG_SMALL;                src = Wd; dst = (uint2*)h_Wd; }
    float4 x = src[o];
    __half2 a = __floats2half2_rn(x.x, x.y);
    __half2 b = __floats2half2_rn(x.z, x.w);
    dst[o] = make_uint2(*(uint32_t*)&a, *(uint32_t*)&b);
}

__global__ void trig_init()
{
    int idx = blockIdx.x * blockDim.x + threadIdx.x;
    int s = idx >> 6, d = idx & 63;
    float inv = exp2f((float)d * -0.20762050593046f);
    float ang = (float)s * inv;
    float sn, cs;
    sincosf(ang, &sn, &cs);
    g_trig[idx] = make_float2(cs, sn);
}

// =========================================================================
// FP16 GEMM: 128-thread CTA (4 warps 2m x 2n), block 128x128, warp tile
// 64x64, K-tile 32, 3-stage cp.async, ldmatrix, occ 3, ONE sync per k-tile.
// =========================================================================
#define AST 40
#define NSTG 3
#define STGH (2 * 128 * AST)
#define GEMM_SMEM (NSTG * STGH * 2)     // 61440 B

template <typename OT>
__global__ void __launch_bounds__(128, 3)
gemm_f16(OT* __restrict__ C, const __half* __restrict__ A,
         const __half* __restrict__ B, int M, int N, int K)
{
    extern __shared__ __half smh[];

    const int tid  = threadIdx.x;
    const int warp = tid >> 5, lane = tid & 31;
    const int wm = warp & 1, wn = warp >> 1;
    const int bm = blockIdx.y * 128, bn = blockIdx.x * 128;
    const int kTiles = K >> 5;
    const uint32_t sbase = smem_u32(smh);

    auto issue = [&](int kt) {
        const int s = kt % NSTG;
        const uint32_t As = sbase + (uint32_t)(s * STGH) * 2;
        const uint32_t Bs = As + 128 * AST * 2;
        const __half* Ag = A + (size_t)bm * K + (size_t)kt * 32;
        const __half* Bg = B + (size_t)bn * K + (size_t)kt * 32;
#pragma unroll
        for (int i = 0; i < 4; i++) {
            int idx = tid + i * 128;
            int r = idx >> 2, c = idx & 3;
            CP_ASYNC16(As + (uint32_t)(r * 80 + c * 16), Ag + (size_t)r * K + c * 8);
        }
#pragma unroll
        for (int i = 0; i < 4; i++) {
            int idx = tid + i * 128;
            int r = idx >> 2, c = idx & 3;
            CP_ASYNC16(Bs + (uint32_t)(r * 80 + c * 16), Bg + (size_t)r * K + c * 8);
        }
        CP_COMMIT();
    };

    float acc[4][8][4];
#pragma unroll
    for (int i = 0; i < 4; i++)
#pragma unroll
        for (int j = 0; j < 8; j++)
#pragma unroll
            for (int t = 0; t < 4; t++) acc[i][j][t] = 0.f;

    const int jj = lane >> 3, rim = lane & 7;
    const int aRow = (jj & 1) * 8 + rim;
    const int aColh = (jj >> 1) * 8;
    const int bRow = (jj >> 1) * 8 + rim;
    const int bColh = (jj & 1) * 8;

    issue(0); issue(1);

    for (int kt = 0; kt < kTiles; kt++) {
        CP_WAIT1();                     // tile kt resident (thread-local)
        __syncthreads();                // visibility + seals compute(kt-1)
        if (kt + 2 < kTiles) issue(kt + 2);
        else CP_COMMIT();

        const int s = kt % NSTG;
        const uint32_t As = sbase + (uint32_t)(s * STGH) * 2;
        const uint32_t Bs = As + 128 * AST * 2;
#pragma unroll
        for (int ks = 0; ks < 2; ks++) {
            uint32_t b[8][2];
#pragma unroll
            for (int p = 0; p < 4; p++) {
                int r = wn * 64 + p * 16 + bRow;
                int ch = ks * 16 + bColh;
                ldsm_x4(b[2 * p][0], b[2 * p][1], b[2 * p + 1][0], b[2 * p + 1][1],
                        Bs + (uint32_t)(r * 80 + ch * 2));
            }
#pragma unroll
            for (int mt = 0; mt < 4; mt++) {
                uint32_t a0, a1, a2, a3;
                int r = wm * 64 + mt * 16 + aRow;
                int ch = ks * 16 + aColh;
                ldsm_x4(a0, a1, a2, a3, As + (uint32_t)(r * 80 + ch * 2));
#pragma unroll
                for (int nt = 0; nt < 8; nt++)
                    mma_f16(acc[mt][nt], a0, a1, a2, a3, b[nt][0], b[nt][1]);
            }
        }
        // no trailing sync: next iteration's leading sync seals this compute
    }

#pragma unroll
    for (int mt = 0; mt < 4; mt++) {
        int r0 = bm + wm * 64 + mt * 16 + (lane >> 2);
#pragma unroll
        for (int nt = 0; nt < 8; nt++) {
            int c0 = bn + wn * 64 + nt * 8 + ((lane & 3) << 1);
            float* c = acc[mt][nt];
            if constexpr (sizeof(OT) == 2) {
                *(__half2*)((__half*)C + (size_t)r0 * N + c0) =
                    __floats2half2_rn(c[0], c[1]);
                *(__half2*)((__half*)C + (size_t)(r0 + 8) * N + c0) =
                    __floats2half2_rn(c[2], c[3]);
            } else {
                *(float2*)((float*)C + (size_t)r0 * N + c0)       = make_float2(c[0], c[1]);
                *(float2*)((float*)C + (size_t)(r0 + 8) * N + c0) = make_float2(c[2], c[3]);
            }
        }
    }
}

// =========================================================================
// Fused RoPE on fp16 (table-driven); folds softmax scale into Q.
// Q in h_Qp (stride 4096); K in h_KVp cols 0..1023 (stride 2048).
// =========================================================================
__global__ void rope_h(__half* __restrict__ Q, __half* __restrict__ KV)
{
    int tok = blockIdx.x;
    int hh  = blockIdx.y * 4 + threadIdx.y;
    int d   = threadIdx.x;
    int s   = tok & 2047;
    float2 t = g_trig[s * 64 + d];
    float cs = t.x, sn = t.y;
    bool isQ = (hh < 32);
    float sc = isQ ? 0.08838834764831845f : 1.0f;
    __half* p = isQ ? (Q + (size_t)tok * 4096 + hh * 128)
                    : (KV + (size_t)tok * 2048 + (hh - 32) * 128);
    float x1 = __half2float(p[d]), x2 = __half2float(p[d + 64]);
    p[d]      = __float2half((x1 * cs - x2 * sn) * sc);
    p[d + 64] = __float2half((x2 * cs + x1 * sn) * sc);
}

// =========================================================================
// Causal flash attention: K/V from combined KVp (stride 2048; V at +1024).
// =========================================================================
#define QH 136
#define TILEB (64 * QH * 2)
#define SS_STR 72

__global__ void __launch_bounds__(256, 2)
attn_kernel(__half* __restrict__ ctx, const __half* __restrict__ Qg,
            const __half* __restrict__ KVg)
{
    extern __shared__ float sm[];
    __half* Qh  = (__half*)sm;
    __half* Kb  = Qh + 64 * QH;
    __half* Vb  = Kb + 2 * 64 * QH;
    float* Ss   = (float*)(Vb + 2 * 64 * QH);
    float* m_sm = Ss + 64 * SS_STR;
    float* l_sm = m_sm + 64;
    float* a_sm = l_sm + 64;

    const int tid  = threadIdx.x;
    const int warp = tid >> 5, lane = tid & 31;
    const int lq = lane >> 2;
    const int lr = lane & 3;
    const int qt = 31 - (int)blockIdx.x;
    const int h  = blockIdx.y;
    const int b  = blockIdx.z;
    const int hkv = h >> 2;

    const int mq = warp & 3;
    const int wh = warp >> 2;

    const uint32_t qb = smem_u32(Qh);
    const uint32_t kb0 = smem_u32(Kb), vb0 = smem_u32(Vb);
    const int jj = lane >> 3, rim = lane & 7;

    const __half* Kbase = KVg + (size_t)(b * 2048) * 2048 + hkv * 128;
    const __half* Vbase = Kbase + 1024;

    auto issue_kv = [&](int kt, int s) {
        const __half* Kp = Kbase + (size_t)(kt * 64) * 2048;
        const __half* Vp = Vbase + (size_t)(kt * 64) * 2048;
        const uint32_t kd = kb0 + (uint32_t)s * TILEB;
        const uint32_t vd = vb0 + (uint32_t)s * TILEB;
#pragma unroll
        for (int i = 0; i < 4; i++) {
            int f = tid + i * 256;
            int r = f >> 4, c = f & 15;
            CP_ASYNC16(kd + (uint32_t)(r * 272 + c * 16), Kp + (size_t)r * 2048 + c * 8);
        }
#pragma unroll
        for (int i = 0; i < 4; i++) {
            int f = tid + i * 256;
            int r = f >> 4, c = f & 15;
            CP_ASYNC16(vd + (uint32_t)(r * 272 + c * 16), Vp + (size_t)r * 2048 + c * 8);
        }
        CP_COMMIT();
    };

    const __half* Qp = Qg + ((size_t)(b * 2048 + qt * 64)) * 4096 + h * 128;
#pragma unroll
    for (int i = 0; i < 4; i++) {
        int f = tid + i * 256;
        int r = f >> 4, c = f & 15;
        *(uint4*)(Qh + r * QH + c * 8) = *(const uint4*)(Qp + (size_t)r * 4096 + c * 8);
    }
    if (tid < 64) { m_sm[tid] = -3.0e38f; l_sm[tid] = 0.f; }

    float O[8][4];
#pragma unroll
    for (int i = 0; i < 8; i++)
#pragma unroll
        for (int j = 0; j < 4; j++) O[i][j] = 0.f;

    issue_kv(0, 0);

    __syncthreads();

    for (int kt = 0; kt <= qt; kt++) {
        const int cur = kt & 1;
        if (kt + 1 <= qt) issue_kv(kt + 1, cur ^ 1);
        else CP_COMMIT();
        CP_WAIT1();
        __syncthreads();

        const uint32_t kb = kb0 + (uint32_t)cur * TILEB;
        const uint32_t vb = vb0 + (uint32_t)cur * TILEB;

        {
            float sacc[4][4];
#pragma unroll
            for (int nt = 0; nt < 4; nt++)
#pragma unroll
                for (int t = 0; t < 4; t++) sacc[nt][t] = 0.f;

#pragma unroll
            for (int ks = 0; ks < 8; ks++) {
                uint32_t a[4], b2[4][2];
                {
                    int r = mq * 16 + (jj & 1) * 8 + rim;
                    int ch = ks * 16 + (jj >> 1) * 8;
                    ldsm_x4(a[0], a[1], a[2], a[3], qb + (uint32_t)(r * 272 + ch * 2));
                }
#pragma unroll
                for (int p = 0; p < 2; p++) {
                    int r = wh * 32 + p * 16 + (jj >> 1) * 8 + rim;
                    int ch = ks * 16 + (jj & 1) * 8;
                    ldsm_x4(b2[2 * p][0], b2[2 * p][1], b2[2 * p + 1][0], b2[2 * p + 1][1],
                            kb + (uint32_t)(r * 272 + ch * 2));
                }
#pragma unroll
                for (int nt = 0; nt < 4; nt++)
                    mma_f16(sacc[nt], a[0], a[1], a[2], a[3], b2[nt][0], b2[nt][1]);
            }
            bool diag = (kt == qt);
#pragma unroll
            for (int nt = 0; nt < 4; nt++) {
                int c = wh * 32 + nt * 8 + 2 * lr;
                float v0 = sacc[nt][0], v1 = sacc[nt][1];
                float v2 = sacc[nt][2], v3 = sacc[nt][3];
                int ra = mq * 16 + lq, rb2 = ra + 8;
                if (diag) {
                    if (c > ra)      v0 = -3.0e38f;
                    if (c + 1 > ra)  v1 = -3.0e38f;
                    if (c > rb2)     v2 = -3.0e38f;
                    if (c + 1 > rb2) v3 = -3.0e38f;
                }
                *(float2*)(Ss + ra * SS_STR + c)  = make_float2(v0, v1);
                *(float2*)(Ss + rb2 * SS_STR + c) = make_float2(v2, v3);
            }
        }
        __syncthreads();

        {
            int row = tid >> 2, seg = tid & 3;
            float* srow = Ss + row * SS_STR;
            float mx = -3.0e38f;
#pragma unroll
            for (int c = 0; c < 16; c++) mx = fmaxf(mx, srow[seg * 16 + c]);
            mx = fmaxf(mx, __shfl_xor_sync(0xffffffffu, mx, 1));
            mx = fmaxf(mx, __shfl_xor_sync(0xffffffffu, mx, 2));
            float m_old = m_sm[row];
            float m_new = fmaxf(m_old, mx);
            float sum = 0.f;
#pragma unroll
            for (int c = 0; c < 16; c++) {
                float p = __expf(srow[seg * 16 + c] - m_new);
                srow[seg * 16 + c] = p;
                sum += p;
            }
            sum += __shfl_xor_sync(0xffffffffu, sum, 1);
            sum += __shfl_xor_sync(0xffffffffu, sum, 2);
            if (seg == 0) {
                float alpha = __expf(m_old - m_new);
                l_sm[row] = l_sm[row] * alpha + sum;
                m_sm[row] = m_new;
                a_sm[row] = alpha;
            }
        }
        __syncthreads();

        {
            const int ra = mq * 16 + lq;
            float al0 = a_sm[ra], al1 = a_sm[ra + 8];
#pragma unroll
            for (int nt = 0; nt < 8; nt++) {
                O[nt][0] *= al0; O[nt][1] *= al0;
                O[nt][2] *= al1; O[nt][3] *= al1;
            }
#pragma unroll
            for (int ks = 0; ks < 4; ks++) {
                const int c0 = ks * 16 + 2 * lr;
                uint32_t a0 = ldcvt(Ss + ra * SS_STR + c0);
                uint32_t a1 = ldcvt(Ss + (ra + 8) * SS_STR + c0);
                uint32_t a2 = ldcvt(Ss + ra * SS_STR + c0 + 8);
                uint32_t a3 = ldcvt(Ss + (ra + 8) * SS_STR + c0 + 8);
                uint32_t b2[8][2];
#pragma unroll
                for (int p = 0; p < 4; p++) {
                    int kr = ks * 16 + (jj & 1) * 8 + rim;
                    int nc = wh * 64 + p * 16 + (jj >> 1) * 8;
                    ldsm_x4t(b2[2 * p][0], b2[2 * p][1], b2[2 * p + 1][0], b2[2 * p + 1][1],
                             vb + (uint32_t)(kr * 272 + nc * 2));
                }
#pragma unroll
                for (int nt = 0; nt < 8; nt++)
                    mma_f16(O[nt], a0, a1, a2, a3, b2[nt][0], b2[nt][1]);
            }
        }
        __syncthreads();
    }

    {
        const int ra = mq * 16 + lq;
        float inv0 = 1.0f / l_sm[ra];
        float inv1 = 1.0f / l_sm[ra + 8];
        __half* Cp = ctx + ((size_t)(b * 2048 + qt * 64)) * 4096 + h * 128;
#pragma unroll
        for (int nt = 0; nt < 8; nt++) {
            int c = wh * 64 + nt * 8 + 2 * lr;
            *(__half2*)(Cp + (size_t)ra * 4096 + c) =
                __floats2half2_rn(O[nt][0] * inv0, O[nt][1] * inv0);
            *(__half2*)(Cp + (size_t)(ra + 8) * 4096 + c) =
                __floats2half2_rn(O[nt][2] * inv1, O[nt][3] * inv1);
        }
    }
}

// =========================================================================
// launcher
// =========================================================================
extern "C" void kernel_launch(void* const* d_in, const int* in_sizes, int n_in,
                              void* d_out, int out_size)
{
    const float* q  = (const float*)d_in[0];
    const float* k  = (const float*)d_in[1];
    const float* v  = (const float*)d_in[2];
    const float* Wq = (const float*)d_in[3];
    const float* Wk = (const float*)d_in[4];
    const float* Wv = (const float*)d_in[5];
    const float* Wd = (const float*)d_in[6];
    float* out = (float*)d_out;

    __half *hq, *hk, *hv, *hWq, *hWkv, *hWd, *hQp, *hKVp, *hctx;
    cudaGetSymbolAddress((void**)&hq,   h_q);
    cudaGetSymbolAddress((void**)&hk,   h_k);
    cudaGetSymbolAddress((void**)&hv,   h_v);
    cudaGetSymbolAddress((void**)&hWq,  h_Wq);
    cudaGetSymbolAddress((void**)&hWkv, h_Wkv);
    cudaGetSymbolAddress((void**)&hWd,  h_Wd);
    cudaGetSymbolAddress((void**)&hQp,  h_Qp);
    cudaGetSymbolAddress((void**)&hKVp, h_KVp);
    cudaGetSymbolAddress((void**)&hctx, h_ctx);

    const int ATTN_SMEM = 5 * 64 * QH * 2 + (64 * SS_STR + 192) * 4;
    cudaFuncSetAttribute(gemm_f16<__half>, cudaFuncAttributeMaxDynamicSharedMemorySize, GEMM_SMEM);
    cudaFuncSetAttribute(gemm_f16<float>,  cudaFuncAttributeMaxDynamicSharedMemorySize, GEMM_SMEM);
    cudaFuncSetAttribute(attn_kernel,      cudaFuncAttributeMaxDynamicSharedMemorySize, ATTN_SMEM);

    f2h_all<<<(F2H_TOTAL + 255) / 256, 256>>>((const float4*)q, (const float4*)k,
                                              (const float4*)v, (const float4*)Wq,
                                              (const float4*)Wk, (const float4*)Wv,
                                              (const float4*)Wd);
    trig_init<<<512, 256>>>();

    // Q projection (fp16 in/out)
    gemm_f16<__half><<<dim3(4096 / 128, 32), 128, GEMM_SMEM>>>(hQp, hq, hWq, 4096, 4096, 4096);
    // Merged K+V projection: note K-proj input is k, V-proj input is v.
    // K cols 0..1023 come from Wk@k; V cols 1024..2047 from Wv@v.
    // Since A differs per half, run as two half-N launches into the SAME
    // output buffer (still better fill than separate outputs? No —
    // actually A differs, so keep two launches but write into combined KVp):
    gemm_f16<__half><<<dim3(1024 / 128, 32), 128, GEMM_SMEM>>>(hKVp, hk, hWkv, 4096, 2048, 4096);
    gemm_f16<__half><<<dim3(1024 / 128, 32), 128, GEMM_SMEM>>>(hKVp + 1024, hv, hWkv + (size_t)1024 * 4096, 4096, 2048, 4096);

    // RoPE on fp16 (table-driven, Q scale folded; K inside KVp)
    rope_h<<<dim3(4096, 10), dim3(64, 4)>>>(hQp, hKVp);

    // attention (fp16 in/out, combined KV)
    attn_kernel<<<dim3(32, 32, 2), 256, ATTN_SMEM>>>(hctx, hQp, hKVp);

    // output projection (fp16 in, fp32 out)
    gemm_f16<float><<<dim3(4096 / 128, 32), 128, GEMM_SMEM>>>(out, hctx, hWd, 4096, 4096, 4096);
}

// round 17
// speedup vs baseline: 1.0160x; 1.0160x over previous
#include <cuda_runtime.h>
#include <cuda_fp16.h>
#include <cstdint>
#include <cstddef>

// ---------------- scratch (all fp16) ----------------
__device__ __half h_q  [16777216];
__device__ __half h_k  [16777216];
__device__ __half h_v  [16777216];
__device__ __half h_Wq [16777216];
__device__ __half h_Wk [ 4194304];
__device__ __half h_Wv [ 4194304];
__device__ __half h_Wd [16777216];
__device__ __half h_Qp [16777216];
__device__ __half h_Kp [ 4194304];
__device__ __half h_Vp [ 4194304];
__device__ __half h_ctx[16777216];
__device__ float2 g_trig[2048 * 64];

// ---------------- helpers ----------------
__device__ __forceinline__ uint32_t smem_u32(const void* p) {
    uint32_t a;
    asm("{ .reg .u64 t; cvta.to.shared.u64 t, %1; cvt.u32.u64 %0, t; }" : "=r"(a) : "l"(p));
    return a;
}
__device__ __forceinline__ void mma_f16(float* c, uint32_t a0, uint32_t a1,
                                        uint32_t a2, uint32_t a3,
                                        uint32_t b0, uint32_t b1) {
    asm volatile(
        "mma.sync.aligned.m16n8k16.row.col.f32.f16.f16.f32 "
        "{%0,%1,%2,%3}, {%4,%5,%6,%7}, {%8,%9}, {%0,%1,%2,%3};\n"
        : "+f"(c[0]), "+f"(c[1]), "+f"(c[2]), "+f"(c[3])
        : "r"(a0), "r"(a1), "r"(a2), "r"(a3), "r"(b0), "r"(b1));
}
__device__ __forceinline__ void ldsm_x4(uint32_t& r0, uint32_t& r1,
                                        uint32_t& r2, uint32_t& r3, uint32_t addr) {
    asm volatile("ldmatrix.sync.aligned.m8n8.x4.shared.b16 {%0,%1,%2,%3}, [%4];"
        : "=r"(r0), "=r"(r1), "=r"(r2), "=r"(r3) : "r"(addr));
}
__device__ __forceinline__ void ldsm_x4t(uint32_t& r0, uint32_t& r1,
                                         uint32_t& r2, uint32_t& r3, uint32_t addr) {
    asm volatile("ldmatrix.sync.aligned.m8n8.x4.trans.shared.b16 {%0,%1,%2,%3}, [%4];"
        : "=r"(r0), "=r"(r1), "=r"(r2), "=r"(r3) : "r"(addr));
}
__device__ __forceinline__ uint32_t ldcvt(const float* p) {
    float2 v = *(const float2*)p;
    __half2 h = __floats2half2_rn(v.x, v.y);
    return *(uint32_t*)&h;
}
#define CP_ASYNC16(dst, src) \
    asm volatile("cp.async.cg.shared.global [%0], [%1], 16;" :: "r"(dst), "l"(src) : "memory")
#define CP_COMMIT() asm volatile("cp.async.commit_group;" ::: "memory")
#define CP_WAIT1()  asm volatile("cp.async.wait_group 1;" ::: "memory")

// =========================================================================
// merged fp32 -> fp16 conversion (one launch)
// =========================================================================
#define SEG_BIG   4194304
#define SEG_SMALL 1048576
#define F2H_TOTAL (5 * SEG_BIG + 2 * SEG_SMALL)

__global__ void f2h_all(const float4* __restrict__ q,  const float4* __restrict__ k,
                        const float4* __restrict__ v,  const float4* __restrict__ Wq,
                        const float4* __restrict__ Wk, const float4* __restrict__ Wv,
                        const float4* __restrict__ Wd)
{
    long i = (long)blockIdx.x * blockDim.x + threadIdx.x;
    if (i >= F2H_TOTAL) return;
    const float4* src;
    uint2* dst;
    long o = i;
    if (o < SEG_BIG)                    { src = q;  dst = (uint2*)h_q; }
    else if ((o -= SEG_BIG) < SEG_BIG)  { src = k;  dst = (uint2*)h_k; }
    else if ((o -= SEG_BIG) < SEG_BIG)  { src = v;  dst = (uint2*)h_v; }
    else if ((o -= SEG_BIG) < SEG_BIG)  { src = Wq; dst = (uint2*)h_Wq; }
    else if ((o -= SEG_BIG) < SEG_SMALL){ src = Wk; dst = (uint2*)h_Wk; }
    else if ((o -= SEG_SMALL) < SEG_SMALL){ src = Wv; dst = (uint2*)h_Wv; }
    else { o -= SEG_SMALL;                src = Wd; dst = (uint2*)h_Wd; }
    float4 x = src[o];
    __half2 a = __floats2half2_rn(x.x, x.y);
    __half2 b = __floats2half2_rn(x.z, x.w);
    dst[o] = make_uint2(*(uint32_t*)&a, *(uint32_t*)&b);
}

__global__ void trig_init()
{
    int idx = blockIdx.x * blockDim.x + threadIdx.x;
    int s = idx >> 6, d = idx & 63;
    float inv = exp2f((float)d * -0.20762050593046f);
    float ang = (float)s * inv;
    float sn, cs;
    sincosf(ang, &sn, &cs);
    g_trig[idx] = make_float2(cs, sn);
}

// =========================================================================
// GEMM core (R15 config): 128-thread CTA (4 warps 2m x 2n), block 128x128,
// warp tile 64x64, K-tile 32 (K=4096 fixed), 3-stage cp.async, ldmatrix.
// =========================================================================
#define AST 40
#define NSTG 3
#define STGH (2 * 128 * AST)
#define GEMM_SMEM (NSTG * STGH * 2)     // 61440 B
#define KDEPTH 4096
#define KTILES (KDEPTH / 32)

template <typename OT>
__device__ __forceinline__ void gemm_body(
    OT* __restrict__ C, const __half* __restrict__ A,
    const __half* __restrict__ B, int N, int bm, int bn, __half* smh)
{
    const int tid  = threadIdx.x;
    const int warp = tid >> 5, lane = tid & 31;
    const int wm = warp & 1, wn = warp >> 1;
    const uint32_t sbase = smem_u32(smh);

    auto issue = [&](int kt) {
        const int s = kt % NSTG;
        const uint32_t As = sbase + (uint32_t)(s * STGH) * 2;
        const uint32_t Bs = As + 128 * AST * 2;
        const __half* Ag = A + (size_t)bm * KDEPTH + (size_t)kt * 32;
        const __half* Bg = B + (size_t)bn * KDEPTH + (size_t)kt * 32;
#pragma unroll
        for (int i = 0; i < 4; i++) {
            int idx = tid + i * 128;
            int r = idx >> 2, c = idx & 3;
            CP_ASYNC16(As + (uint32_t)(r * 80 + c * 16), Ag + (size_t)r * KDEPTH + c * 8);
        }
#pragma unroll
        for (int i = 0; i < 4; i++) {
            int idx = tid + i * 128;
            int r = idx >> 2, c = idx & 3;
            CP_ASYNC16(Bs + (uint32_t)(r * 80 + c * 16), Bg + (size_t)r * KDEPTH + c * 8);
        }
        CP_COMMIT();
    };

    float acc[4][8][4];
#pragma unroll
    for (int i = 0; i < 4; i++)
#pragma unroll
        for (int j = 0; j < 8; j++)
#pragma unroll
            for (int t = 0; t < 4; t++) acc[i][j][t] = 0.f;

    const int jj = lane >> 3, rim = lane & 7;
    const int aRow = (jj & 1) * 8 + rim;
    const int aColh = (jj >> 1) * 8;
    const int bRow = (jj >> 1) * 8 + rim;
    const int bColh = (jj & 1) * 8;

    issue(0); issue(1);

    for (int kt = 0; kt < KTILES; kt++) {
        CP_WAIT1();
        __syncthreads();
        if (kt + 2 < KTILES) issue(kt + 2);
        else CP_COMMIT();

        const int s = kt % NSTG;
        const uint32_t As = sbase + (uint32_t)(s * STGH) * 2;
        const uint32_t Bs = As + 128 * AST * 2;
#pragma unroll
        for (int ks = 0; ks < 2; ks++) {
            uint32_t b[8][2];
#pragma unroll
            for (int p = 0; p < 4; p++) {
                int r = wn * 64 + p * 16 + bRow;
                int ch = ks * 16 + bColh;
                ldsm_x4(b[2 * p][0], b[2 * p][1], b[2 * p + 1][0], b[2 * p + 1][1],
                        Bs + (uint32_t)(r * 80 + ch * 2));
            }
#pragma unroll
            for (int mt = 0; mt < 4; mt++) {
                uint32_t a0, a1, a2, a3;
                int r = wm * 64 + mt * 16 + aRow;
                int ch = ks * 16 + aColh;
                ldsm_x4(a0, a1, a2, a3, As + (uint32_t)(r * 80 + ch * 2));
#pragma unroll
                for (int nt = 0; nt < 8; nt++)
                    mma_f16(acc[mt][nt], a0, a1, a2, a3, b[nt][0], b[nt][1]);
            }
        }
        __syncthreads();
    }

#pragma unroll
    for (int mt = 0; mt < 4; mt++) {
        int r0 = bm + wm * 64 + mt * 16 + (lane >> 2);
#pragma unroll
        for (int nt = 0; nt < 8; nt++) {
            int c0 = bn + wn * 64 + nt * 8 + ((lane & 3) << 1);
            float* c = acc[mt][nt];
            if constexpr (sizeof(OT) == 2) {
                *(__half2*)((__half*)C + (size_t)r0 * N + c0) =
                    __floats2half2_rn(c[0], c[1]);
                *(__half2*)((__half*)C + (size_t)(r0 + 8) * N + c0) =
                    __floats2half2_rn(c[2], c[3]);
            } else {
                *(float2*)((float*)C + (size_t)r0 * N + c0)       = make_float2(c[0], c[1]);
                *(float2*)((float*)C + (size_t)(r0 + 8) * N + c0) = make_float2(c[2], c[3]);
            }
        }
    }
}

// Merged Q/K/V projection: flat 1536-CTA grid.
// blocks [0,1024): Q (N=4096); [1024,1280): K (N=1024); [1280,1536): V.
__global__ void __launch_bounds__(128, 3)
qkv_proj()
{
    extern __shared__ __half smh[];
    int id = blockIdx.x;
    if (id < 1024) {
        int bn = (id & 31) * 128, bm = (id >> 5) * 128;
        gemm_body<__half>(h_Qp, h_q, h_Wq, 4096, bm, bn, smh);
    } else if (id < 1280) {
        int r = id - 1024;
        int bn = (r & 7) * 128, bm = (r >> 3) * 128;
        gemm_body<__half>(h_Kp, h_k, h_Wk, 1024, bm, bn, smh);
    } else {
        int r = id - 1280;
        int bn = (r & 7) * 128, bm = (r >> 3) * 128;
        gemm_body<__half>(h_Vp, h_v, h_Wv, 1024, bm, bn, smh);
    }
}

// Output projection (fp32 out)
__global__ void __launch_bounds__(128, 3)
out_proj(float* __restrict__ C)
{
    extern __shared__ __half smh[];
    int bn = (int)blockIdx.x * 128, bm = (int)blockIdx.y * 128;
    gemm_body<float>(C, h_ctx, h_Wd, 4096, bm, bn, smh);
}

// =========================================================================
// Fused RoPE on fp16 (table-driven); folds softmax scale into Q.
// =========================================================================
__global__ void rope_h(__half* __restrict__ Q, __half* __restrict__ K)
{
    int tok = blockIdx.x;
    int hh  = blockIdx.y * 4 + threadIdx.y;
    int d   = threadIdx.x;
    int s   = tok & 2047;
    float2 t = g_trig[s * 64 + d];
    float cs = t.x, sn = t.y;
    bool isQ = (hh < 32);
    float sc = isQ ? 0.08838834764831845f : 1.0f;
    __half* p = isQ ? (Q + (size_t)tok * 4096 + hh * 128)
                    : (K + (size_t)tok * 1024 + (hh - 32) * 128);
    float x1 = __half2float(p[d]), x2 = __half2float(p[d + 64]);
    p[d]      = __float2half((x1 * cs - x2 * sn) * sc);
    p[d + 64] = __float2half((x2 * cs + x1 * sn) * sc);
}

// =========================================================================
// Causal flash attention (R15 config, unchanged)
// =========================================================================
#define QH 136
#define TILEB (64 * QH * 2)
#define SS_STR 72

__global__ void __launch_bounds__(256, 2)
attn_kernel(__half* __restrict__ ctx, const __half* __restrict__ Qg,
            const __half* __restrict__ Kg, const __half* __restrict__ Vg)
{
    extern __shared__ float sm[];
    __half* Qh  = (__half*)sm;
    __half* Kb  = Qh + 64 * QH;
    __half* Vb  = Kb + 2 * 64 * QH;
    float* Ss   = (float*)(Vb + 2 * 64 * QH);
    float* m_sm = Ss + 64 * SS_STR;
    float* l_sm = m_sm + 64;
    float* a_sm = l_sm + 64;

    const int tid  = threadIdx.x;
    const int warp = tid >> 5, lane = tid & 31;
    const int lq = lane >> 2;
    const int lr = lane & 3;
    const int qt = 31 - (int)blockIdx.x;
    const int h  = blockIdx.y;
    const int b  = blockIdx.z;
    const int hkv = h >> 2;

    const int mq = warp & 3;
    const int wh = warp >> 2;

    const uint32_t qb = smem_u32(Qh);
    const uint32_t kb0 = smem_u32(Kb), vb0 = smem_u32(Vb);
    const int jj = lane >> 3, rim = lane & 7;

    const __half* Kbase = Kg + (size_t)(b * 2048) * 1024 + hkv * 128;
    const __half* Vbase = Vg + (size_t)(b * 2048) * 1024 + hkv * 128;

    auto issue_kv = [&](int kt, int s) {
        const __half* Kp = Kbase + (size_t)(kt * 64) * 1024;
        const __half* Vp = Vbase + (size_t)(kt * 64) * 1024;
        const uint32_t kd = kb0 + (uint32_t)s * TILEB;
        const uint32_t vd = vb0 + (uint32_t)s * TILEB;
#pragma unroll
        for (int i = 0; i < 4; i++) {
            int f = tid + i * 256;
            int r = f >> 4, c = f & 15;
            CP_ASYNC16(kd + (uint32_t)(r * 272 + c * 16), Kp + (size_t)r * 1024 + c * 8);
        }
#pragma unroll
        for (int i = 0; i < 4; i++) {
            int f = tid + i * 256;
            int r = f >> 4, c = f & 15;
            CP_ASYNC16(vd + (uint32_t)(r * 272 + c * 16), Vp + (size_t)r * 1024 + c * 8);
        }
        CP_COMMIT();
    };

    const __half* Qp = Qg + ((size_t)(b * 2048 + qt * 64)) * 4096 + h * 128;
#pragma unroll
    for (int i = 0; i < 4; i++) {
        int f = tid + i * 256;
        int r = f >> 4, c = f & 15;
        *(uint4*)(Qh + r * QH + c * 8) = *(const uint4*)(Qp + (size_t)r * 4096 + c * 8);
    }
    if (tid < 64) { m_sm[tid] = -3.0e38f; l_sm[tid] = 0.f; }

    float O[8][4];
#pragma unroll
    for (int i = 0; i < 8; i++)
#pragma unroll
        for (int j = 0; j < 4; j++) O[i][j] = 0.f;

    issue_kv(0, 0);

    __syncthreads();

    for (int kt = 0; kt <= qt; kt++) {
        const int cur = kt & 1;
        if (kt + 1 <= qt) issue_kv(kt + 1, cur ^ 1);
        else CP_COMMIT();
        CP_WAIT1();
        __syncthreads();

        const uint32_t kb = kb0 + (uint32_t)cur * TILEB;
        const uint32_t vb = vb0 + (uint32_t)cur * TILEB;

        {
            float sacc[4][4];
#pragma unroll
            for (int nt = 0; nt < 4; nt++)
#pragma unroll
                for (int t = 0; t < 4; t++) sacc[nt][t] = 0.f;

#pragma unroll
            for (int ks = 0; ks < 8; ks++) {
                uint32_t a[4], b2[4][2];
                {
                    int r = mq * 16 + (jj & 1) * 8 + rim;
                    int ch = ks * 16 + (jj >> 1) * 8;
                    ldsm_x4(a[0], a[1], a[2], a[3], qb + (uint32_t)(r * 272 + ch * 2));
                }
#pragma unroll
                for (int p = 0; p < 2; p++) {
                    int r = wh * 32 + p * 16 + (jj >> 1) * 8 + rim;
                    int ch = ks * 16 + (jj & 1) * 8;
                    ldsm_x4(b2[2 * p][0], b2[2 * p][1], b2[2 * p + 1][0], b2[2 * p + 1][1],
                            kb + (uint32_t)(r * 272 + ch * 2));
                }
#pragma unroll
                for (int nt = 0; nt < 4; nt++)
                    mma_f16(sacc[nt], a[0], a[1], a[2], a[3], b2[nt][0], b2[nt][1]);
            }
            bool diag = (kt == qt);
#pragma unroll
            for (int nt = 0; nt < 4; nt++) {
                int c = wh * 32 + nt * 8 + 2 * lr;
                float v0 = sacc[nt][0], v1 = sacc[nt][1];
                float v2 = sacc[nt][2], v3 = sacc[nt][3];
                int ra = mq * 16 + lq, rb2 = ra + 8;
                if (diag) {
                    if (c > ra)      v0 = -3.0e38f;
                    if (c + 1 > ra)  v1 = -3.0e38f;
                    if (c > rb2)     v2 = -3.0e38f;
                    if (c + 1 > rb2) v3 = -3.0e38f;
                }
                *(float2*)(Ss + ra * SS_STR + c)  = make_float2(v0, v1);
                *(float2*)(Ss + rb2 * SS_STR + c) = make_float2(v2, v3);
            }
        }
        __syncthreads();

        {
            int row = tid >> 2, seg = tid & 3;
            float* srow = Ss + row * SS_STR;
            float mx = -3.0e38f;
#pragma unroll
            for (int c = 0; c < 16; c++) mx = fmaxf(mx, srow[seg * 16 + c]);
            mx = fmaxf(mx, __shfl_xor_sync(0xffffffffu, mx, 1));
            mx = fmaxf(mx, __shfl_xor_sync(0xffffffffu, mx, 2));
            float m_old = m_sm[row];
            float m_new = fmaxf(m_old, mx);
            float sum = 0.f;
#pragma unroll
            for (int c = 0; c < 16; c++) {
                float p = __expf(srow[seg * 16 + c] - m_new);
                srow[seg * 16 + c] = p;
                sum += p;
            }
            sum += __shfl_xor_sync(0xffffffffu, sum, 1);
            sum += __shfl_xor_sync(0xffffffffu, sum, 2);
            if (seg == 0) {
                float alpha = __expf(m_old - m_new);
                l_sm[row] = l_sm[row] * alpha + sum;
                m_sm[row] = m_new;
                a_sm[row] = alpha;
            }
        }
        __syncthreads();

        {
            const int ra = mq * 16 + lq;
            float al0 = a_sm[ra], al1 = a_sm[ra + 8];
#pragma unroll
            for (int nt = 0; nt < 8; nt++) {
                O[nt][0] *= al0; O[nt][1] *= al0;
                O[nt][2] *= al1; O[nt][3] *= al1;
            }
#pragma unroll
            for (int ks = 0; ks < 4; ks++) {
                const int c0 = ks * 16 + 2 * lr;
                uint32_t a0 = ldcvt(Ss + ra * SS_STR + c0);
                uint32_t a1 = ldcvt(Ss + (ra + 8) * SS_STR + c0);
                uint32_t a2 = ldcvt(Ss + ra * SS_STR + c0 + 8);
                uint32_t a3 = ldcvt(Ss + (ra + 8) * SS_STR + c0 + 8);
                uint32_t b2[8][2];
#pragma unroll
                for (int p = 0; p < 4; p++) {
                    int kr = ks * 16 + (jj & 1) * 8 + rim;
                    int nc = wh * 64 + p * 16 + (jj >> 1) * 8;
                    ldsm_x4t(b2[2 * p][0], b2[2 * p][1], b2[2 * p + 1][0], b2[2 * p + 1][1],
                             vb + (uint32_t)(kr * 272 + nc * 2));
                }
#pragma unroll
                for (int nt = 0; nt < 8; nt++)
                    mma_f16(O[nt], a0, a1, a2, a3, b2[nt][0], b2[nt][1]);
            }
        }
        __syncthreads();
    }

    {
        const int ra = mq * 16 + lq;
        float inv0 = 1.0f / l_sm[ra];
        float inv1 = 1.0f / l_sm[ra + 8];
        __half* Cp = ctx + ((size_t)(b * 2048 + qt * 64)) * 4096 + h * 128;
#pragma unroll
        for (int nt = 0; nt < 8; nt++) {
            int c = wh * 64 + nt * 8 + 2 * lr;
            *(__half2*)(Cp + (size_t)ra * 4096 + c) =
                __floats2half2_rn(O[nt][0] * inv0, O[nt][1] * inv0);
            *(__half2*)(Cp + (size_t)(ra + 8) * 4096 + c) =
                __floats2half2_rn(O[nt][2] * inv1, O[nt][3] * inv1);
        }
    }
}

// =========================================================================
// launcher
// =========================================================================
extern "C" void kernel_launch(void* const* d_in, const int* in_sizes, int n_in,
                              void* d_out, int out_size)
{
    const float* q  = (const float*)d_in[0];
    const float* k  = (const float*)d_in[1];
    const float* v  = (const float*)d_in[2];
    const float* Wq = (const float*)d_in[3];
    const float* Wk = (const float*)d_in[4];
    const float* Wv = (const float*)d_in[5];
    const float* Wd = (const float*)d_in[6];
    float* out = (float*)d_out;

    __half *hQp, *hKp, *hVp, *hctx;
    cudaGetSymbolAddress((void**)&hQp,  h_Qp);
    cudaGetSymbolAddress((void**)&hKp,  h_Kp);
    cudaGetSymbolAddress((void**)&hVp,  h_Vp);
    cudaGetSymbolAddress((void**)&hctx, h_ctx);

    const int ATTN_SMEM = 5 * 64 * QH * 2 + (64 * SS_STR + 192) * 4;
    cudaFuncSetAttribute(qkv_proj,    cudaFuncAttributeMaxDynamicSharedMemorySize, GEMM_SMEM);
    cudaFuncSetAttribute(out_proj,    cudaFuncAttributeMaxDynamicSharedMemorySize, GEMM_SMEM);
    cudaFuncSetAttribute(attn_kernel, cudaFuncAttributeMaxDynamicSharedMemorySize, ATTN_SMEM);

    f2h_all<<<(F2H_TOTAL + 255) / 256, 256>>>((const float4*)q, (const float4*)k,
                                              (const float4*)v, (const float4*)Wq,
                                              (const float4*)Wk, (const float4*)Wv,
                                              (const float4*)Wd);
    trig_init<<<512, 256>>>();

    // merged Q/K/V projections — one 1536-CTA launch
    qkv_proj<<<1536, 128, GEMM_SMEM>>>();

    // RoPE on fp16 (table-driven, Q scale folded)
    rope_h<<<dim3(4096, 10), dim3(64, 4)>>>(hQp, hKp);

    // attention (fp16 in/out)
    attn_kernel<<<dim3(32, 32, 2), 256, ATTN_SMEM>>>(hctx, hQp, hKp, hVp);

    // output projection (fp16 in, fp32 out)
    out_proj<<<dim3(32, 32), 128, GEMM_SMEM>>>(out);
}